// round 12
// baseline (speedup 1.0000x reference)
#include <cuda_runtime.h>
#include <cuda_fp16.h>
#include <cstdint>

#define Bc 4
#define Tc 2048
#define Cc 1024
#define Dc 64
#define BT (Bc*Tc)

#define QT   128
#define NQ2  (Tc/QT)
#define SCH  4
#define MAXC2 8
#define SKS2 72            // attn K/V smem row stride in halves (144B, ≡4w mod 32)
#define SA2  72            // qkv smem row stride in halves (BKH=64 + pad 8)
#define BKH  64            // qkv k-chunk in halves

// Scratch (allocation-free rule => __device__ globals)
__device__ __half g_xh [(size_t)BT*Cc];              // fp16 x
__device__ __half g_WhT[3*Dc*Cc];                    // fp16 W^T [proj][n][k]
__device__ __half g_Qh [BT*Dc];                      // fp16 Q (pre-scaled)
__device__ __half g_Kh [BT*Dc];
__device__ __half g_Vh [BT*Dc];
__device__ __half g_Op2h[(size_t)Bc*NQ2*MAXC2*QT*Dc];   // fp16 partials
__device__ float  g_m2[Bc*NQ2*MAXC2*QT];
__device__ float  g_l2[Bc*NQ2*MAXC2*QT];

__device__ __forceinline__ unsigned packh2(float lo, float hi) {
    __half2 h = __floats2half2_rn(lo, hi);
    return *(unsigned*)&h;
}

__device__ __forceinline__ unsigned smem_u32(const void* p) {
    return (unsigned)__cvta_generic_to_shared(p);
}

__device__ __forceinline__ void mma_f16(float c[4], unsigned a0, unsigned a1,
                                        unsigned a2, unsigned a3,
                                        unsigned b0, unsigned b1) {
    asm volatile(
        "mma.sync.aligned.m16n8k16.row.col.f32.f16.f16.f32 "
        "{%0,%1,%2,%3}, {%4,%5,%6,%7}, {%8,%9}, {%0,%1,%2,%3};"
        : "+f"(c[0]), "+f"(c[1]), "+f"(c[2]), "+f"(c[3])
        : "r"(a0), "r"(a1), "r"(a2), "r"(a3), "r"(b0), "r"(b1));
}

__device__ __forceinline__ void ldsm_x4(unsigned& r0, unsigned& r1,
                                        unsigned& r2, unsigned& r3, unsigned a) {
    asm volatile("ldmatrix.sync.aligned.m8n8.x4.shared.b16 {%0,%1,%2,%3}, [%4];"
                 : "=r"(r0), "=r"(r1), "=r"(r2), "=r"(r3) : "r"(a));
}
__device__ __forceinline__ void ldsm_x4_t(unsigned& r0, unsigned& r1,
                                          unsigned& r2, unsigned& r3, unsigned a) {
    asm volatile("ldmatrix.sync.aligned.m8n8.x4.trans.shared.b16 {%0,%1,%2,%3}, [%4];"
                 : "=r"(r0), "=r"(r1), "=r"(r2), "=r"(r3) : "r"(a));
}

__device__ __forceinline__ void cp16(void* dst_smem, const void* src) {
    unsigned d = (unsigned)__cvta_generic_to_shared(dst_smem);
    asm volatile("cp.async.ca.shared.global [%0], [%1], 16;" :: "r"(d), "l"(src));
}
#define CP_COMMIT() asm volatile("cp.async.commit_group;")
#define CP_WAIT1()  asm volatile("cp.async.wait_group 1;")

// ---------------------------------------------------------------------------
// Kernel 0a: x -> fp16.  grid = 4096, block 256.
// ---------------------------------------------------------------------------
__global__ __launch_bounds__(256) void prepx_kernel(const float* __restrict__ x)
{
    size_t idx = (size_t)blockIdx.x * 256 + threadIdx.x;
    const float4* xg = (const float4*)x;
    float4 v0 = xg[2*idx], v1 = xg[2*idx + 1];
    __half2 h0 = __floats2half2_rn(v0.x, v0.y);
    __half2 h1 = __floats2half2_rn(v0.z, v0.w);
    __half2 h2 = __floats2half2_rn(v1.x, v1.y);
    __half2 h3 = __floats2half2_rn(v1.z, v1.w);
    uint4 o;
    o.x = *(unsigned*)&h0; o.y = *(unsigned*)&h1;
    o.z = *(unsigned*)&h2; o.w = *(unsigned*)&h3;
    ((uint4*)g_xh)[idx] = o;
}

// ---------------------------------------------------------------------------
// Kernel 0b: W^T -> fp16.  grid = 768, block 256.
// ---------------------------------------------------------------------------
__global__ __launch_bounds__(256) void prepw_kernel(
    const float* __restrict__ Wq, const float* __restrict__ Wk,
    const float* __restrict__ Wv)
{
    int e = blockIdx.x * 256 + threadIdx.x;
    int proj = e >> 16;
    int r = e & 65535;
    int k = r >> 6;
    int n = r & 63;
    const float* W = (proj == 0) ? Wq : (proj == 1) ? Wk : Wv;
    g_WhT[(size_t)proj*(Dc*Cc) + (size_t)n*Cc + k] = __float2half_rn(W[(size_t)k*Dc + n]);
}

// ---------------------------------------------------------------------------
// Kernel 1: QKV projection, fp16 m16n8k16 + ldmatrix, k-chunk 64, 2-stage.
// grid = (BT/64, 3), block = 128 (4 warps). Tile 64x64.
// ---------------------------------------------------------------------------
__global__ __launch_bounds__(128) void qkv_kernel(
    const float* __restrict__ bq, const float* __restrict__ bk,
    const float* __restrict__ bv)
{
    extern __shared__ __align__(16) __half sm[];
    __half* As = sm;                    // [2][64*SA2]
    __half* Bs = sm + 2*64*SA2;         // [2][64*SA2]

    const int tid = threadIdx.x;
    const int which = blockIdx.y;
    const __half* WT = g_WhT + (size_t)which * (Dc*Cc);
    const float* bias = (which == 0) ? bq : (which == 1) ? bk : bv;
    __half* O = (which == 0) ? g_Qh : (which == 1) ? g_Kh : g_Vh;
    const float osc = (which == 0) ? 0.125f : 1.0f;

    const int m0 = blockIdx.x * 64;
    const int w  = tid >> 5;
    const int lane = tid & 31;
    const int g  = lane >> 2;
    const int tg = lane & 3;
    const int wm = (w & 1) * 32;
    const int wn = (w >> 1) * 32;

    const int lr8 = lane & 7;
    const int lm1 = (lane >> 3) & 1;
    const int lm2 = lane >> 4;

    // staging: row = tid>>1 (0..63), half-row = tid&1; 4 cp16 (64B) per thread
    const int l_row = tid >> 1;
    const int l_hf  = (tid & 1) * 32;    // half offset within 64-half row

    float acc[2][4][4];
    #pragma unroll
    for (int mt = 0; mt < 2; ++mt)
        #pragma unroll
        for (int nt = 0; nt < 4; ++nt)
            #pragma unroll
            for (int q = 0; q < 4; ++q) acc[mt][nt][q] = 0.f;

    // Prologue: stage kc=0
    {
        #pragma unroll
        for (int j = 0; j < 4; ++j) {
            cp16(&As[l_row*SA2 + l_hf + j*8], &g_xh[(size_t)(m0 + l_row)*Cc + l_hf + j*8]);
            cp16(&Bs[l_row*SA2 + l_hf + j*8], &WT[(size_t)l_row*Cc + l_hf + j*8]);
        }
        CP_COMMIT();
    }

    const int NIT = Cc / BKH;            // 16
    for (int kc = 0; kc < NIT; ++kc) {
        const int buf = kc & 1;
        __half* Ab = As + buf*64*SA2;
        __half* Bb = Bs + buf*64*SA2;
        __half* An = As + (buf^1)*64*SA2;
        __half* Bn = Bs + (buf^1)*64*SA2;

        __syncthreads();
        if (kc + 1 < NIT) {
            #pragma unroll
            for (int j = 0; j < 4; ++j) {
                cp16(&An[l_row*SA2 + l_hf + j*8],
                     &g_xh[(size_t)(m0 + l_row)*Cc + (kc+1)*BKH + l_hf + j*8]);
                cp16(&Bn[l_row*SA2 + l_hf + j*8],
                     &WT[(size_t)l_row*Cc + (kc+1)*BKH + l_hf + j*8]);
            }
        }
        CP_COMMIT();
        CP_WAIT1();
        __syncthreads();

        #pragma unroll
        for (int ks = 0; ks < 4; ++ks) {
            const int k0 = ks * 16;
            unsigned a[2][4], b[4][2];
            #pragma unroll
            for (int mt = 0; mt < 2; ++mt) {
                unsigned ad = smem_u32(
                    &Ab[(wm + mt*16 + lr8 + lm1*8)*SA2 + k0 + lm2*8]);
                ldsm_x4(a[mt][0], a[mt][1], a[mt][2], a[mt][3], ad);
            }
            #pragma unroll
            for (int ntp = 0; ntp < 2; ++ntp) {
                unsigned bd = smem_u32(
                    &Bb[(wn + ntp*16 + lr8 + lm2*8)*SA2 + k0 + lm1*8]);
                ldsm_x4(b[ntp*2][0], b[ntp*2][1], b[ntp*2+1][0], b[ntp*2+1][1], bd);
            }
            #pragma unroll
            for (int mt = 0; mt < 2; ++mt)
                #pragma unroll
                for (int nt = 0; nt < 4; ++nt)
                    mma_f16(acc[mt][nt], a[mt][0], a[mt][1], a[mt][2], a[mt][3],
                            b[nt][0], b[nt][1]);
        }
    }

    // Writeback fp16 (Q scaled by 1/8)
    #pragma unroll
    for (int nt = 0; nt < 4; ++nt) {
        const int col = wn + nt*8 + 2*tg;
        float bx = bias[col], by = bias[col+1];
        #pragma unroll
        for (int mt = 0; mt < 2; ++mt) {
            int row = m0 + wm + mt*16 + g;
            __half2 h0 = __floats2half2_rn((acc[mt][nt][0]+bx)*osc, (acc[mt][nt][1]+by)*osc);
            __half2 h1 = __floats2half2_rn((acc[mt][nt][2]+bx)*osc, (acc[mt][nt][3]+by)*osc);
            *(__half2*)&O[(size_t)row*Dc + col]     = h0;
            *(__half2*)&O[(size_t)(row+8)*Dc + col] = h1;
        }
    }
}

// ---------------------------------------------------------------------------
// Kernel 2: fp16 m16n8k16 flash attention, split-KV, cp.async + ldmatrix.
// grid = (MAXC2, NQ2, B), block = 256 (8 warps). fp16 partial output.
// ---------------------------------------------------------------------------
__global__ __launch_bounds__(256, 2) void attn_kernel()
{
    const int c = blockIdx.x;
    const int i = blockIdx.y;
    const int b = blockIdx.z;
    const int ktot = 2*(i+1);
    const int kt0 = c * SCH;
    if (kt0 >= ktot) return;
    const int kt1 = min(kt0 + SCH, ktot);

    extern __shared__ __align__(16) __half smem[];
    __half* Ksm = smem;                  // [2][64*SKS2]
    __half* Vsm = smem + 2*64*SKS2;      // [2][64*SKS2]

    const int tid = threadIdx.x;
    const int w = tid >> 5, lane = tid & 31;
    const int g = lane >> 2, tg = lane & 3;
    const int qrow = i*QT + w*16;
    const size_t bT = (size_t)b * Tc;

    const int lr8 = lane & 7;
    const int lm1 = (lane >> 3) & 1;
    const int lm2 = lane >> 4;

    const int l_row = tid >> 2;          // 0..63
    const int l_c16 = tid & 3;           // 0..3

    // Prologue: stage tile kt0
    {
        const __half* Kg = &g_Kh[(bT + kt0*64 + l_row)*Dc];
        const __half* Vg = &g_Vh[(bT + kt0*64 + l_row)*Dc];
        cp16(&Ksm[l_row*SKS2 + l_c16*8],      Kg + l_c16*8);
        cp16(&Ksm[l_row*SKS2 + 32 + l_c16*8], Kg + 32 + l_c16*8);
        cp16(&Vsm[l_row*SKS2 + l_c16*8],      Vg + l_c16*8);
        cp16(&Vsm[l_row*SKS2 + 32 + l_c16*8], Vg + 32 + l_c16*8);
        CP_COMMIT();
    }

    // Q A-fragments
    unsigned qa[4][4];
    {
        const __half* Qp = &g_Qh[(bT + qrow)*Dc];
        #pragma unroll
        for (int kc = 0; kc < 4; ++kc) {
            qa[kc][0] = *(const unsigned*)&Qp[(g  )*Dc + kc*16 + 2*tg];
            qa[kc][1] = *(const unsigned*)&Qp[(g+8)*Dc + kc*16 + 2*tg];
            qa[kc][2] = *(const unsigned*)&Qp[(g  )*Dc + kc*16 + 8 + 2*tg];
            qa[kc][3] = *(const unsigned*)&Qp[(g+8)*Dc + kc*16 + 8 + 2*tg];
        }
    }

    float o[8][4];
    #pragma unroll
    for (int nt = 0; nt < 8; ++nt)
        #pragma unroll
        for (int q = 0; q < 4; ++q) o[nt][q] = 0.f;
    float m0v = -1e30f, m1v = -1e30f, l0 = 0.f, l1 = 0.f;

    for (int kt = kt0; kt < kt1; ++kt) {
        const int buf = (kt - kt0) & 1;
        const __half* ks = Ksm + buf*64*SKS2;
        const __half* vs = Vsm + buf*64*SKS2;
        __half* kn = Ksm + (buf^1)*64*SKS2;
        __half* vn = Vsm + (buf^1)*64*SKS2;

        __syncthreads();
        if (kt + 1 < kt1) {
            const __half* Kg = &g_Kh[(bT + (kt+1)*64 + l_row)*Dc];
            const __half* Vg = &g_Vh[(bT + (kt+1)*64 + l_row)*Dc];
            cp16(&kn[l_row*SKS2 + l_c16*8],      Kg + l_c16*8);
            cp16(&kn[l_row*SKS2 + 32 + l_c16*8], Kg + 32 + l_c16*8);
            cp16(&vn[l_row*SKS2 + l_c16*8],      Vg + l_c16*8);
            cp16(&vn[l_row*SKS2 + 32 + l_c16*8], Vg + 32 + l_c16*8);
        }
        CP_COMMIT();
        CP_WAIT1();
        __syncthreads();

        const int kb = kt * 64;
        if (kb <= qrow + 15) {
            // --- S = Q @ K^T ---
            float s[8][4];
            #pragma unroll
            for (int nt = 0; nt < 8; ++nt)
                { s[nt][0]=0.f; s[nt][1]=0.f; s[nt][2]=0.f; s[nt][3]=0.f; }
            #pragma unroll
            for (int kc = 0; kc < 4; ++kc) {
                unsigned kb_[8][2];
                #pragma unroll
                for (int ntp = 0; ntp < 4; ++ntp) {
                    unsigned ad = smem_u32(
                        &ks[(ntp*16 + lr8 + lm2*8)*SKS2 + kc*16 + lm1*8]);
                    ldsm_x4(kb_[ntp*2][0], kb_[ntp*2][1],
                            kb_[ntp*2+1][0], kb_[ntp*2+1][1], ad);
                }
                #pragma unroll
                for (int nt = 0; nt < 8; ++nt)
                    mma_f16(s[nt], qa[kc][0], qa[kc][1], qa[kc][2], qa[kc][3],
                            kb_[nt][0], kb_[nt][1]);
            }

            // --- causal mask ---
            if (kb + 63 > qrow) {
                const int r0 = qrow + g, r1 = r0 + 8;
                #pragma unroll
                for (int nt = 0; nt < 8; ++nt) {
                    int col = kb + nt*8 + 2*tg;
                    if (col   > r0) s[nt][0] = -1e30f;
                    if (col+1 > r0) s[nt][1] = -1e30f;
                    if (col   > r1) s[nt][2] = -1e30f;
                    if (col+1 > r1) s[nt][3] = -1e30f;
                }
            }

            // --- online softmax ---
            float rm0 = -1e30f, rm1 = -1e30f;
            #pragma unroll
            for (int nt = 0; nt < 8; ++nt) {
                rm0 = fmaxf(rm0, fmaxf(s[nt][0], s[nt][1]));
                rm1 = fmaxf(rm1, fmaxf(s[nt][2], s[nt][3]));
            }
            rm0 = fmaxf(rm0, __shfl_xor_sync(0xffffffffu, rm0, 1));
            rm0 = fmaxf(rm0, __shfl_xor_sync(0xffffffffu, rm0, 2));
            rm1 = fmaxf(rm1, __shfl_xor_sync(0xffffffffu, rm1, 1));
            rm1 = fmaxf(rm1, __shfl_xor_sync(0xffffffffu, rm1, 2));
            const float mn0 = fmaxf(m0v, rm0), mn1 = fmaxf(m1v, rm1);
            const float f0 = __expf(m0v - mn0), f1 = __expf(m1v - mn1);
            m0v = mn0; m1v = mn1;

            float rs0 = 0.f, rs1 = 0.f;
            #pragma unroll
            for (int nt = 0; nt < 8; ++nt) {
                s[nt][0] = __expf(s[nt][0] - mn0);
                s[nt][1] = __expf(s[nt][1] - mn0);
                s[nt][2] = __expf(s[nt][2] - mn1);
                s[nt][3] = __expf(s[nt][3] - mn1);
                rs0 += s[nt][0] + s[nt][1];
                rs1 += s[nt][2] + s[nt][3];
            }
            rs0 += __shfl_xor_sync(0xffffffffu, rs0, 1);
            rs0 += __shfl_xor_sync(0xffffffffu, rs0, 2);
            rs1 += __shfl_xor_sync(0xffffffffu, rs1, 1);
            rs1 += __shfl_xor_sync(0xffffffffu, rs1, 2);
            l0 = l0*f0 + rs0;
            l1 = l1*f1 + rs1;
            #pragma unroll
            for (int nt = 0; nt < 8; ++nt) {
                o[nt][0] *= f0; o[nt][1] *= f0;
                o[nt][2] *= f1; o[nt][3] *= f1;
            }

            // --- O += P @ V ---
            #pragma unroll
            for (int kc = 0; kc < 4; ++kc) {
                unsigned pa0 = packh2(s[2*kc  ][0], s[2*kc  ][1]);
                unsigned pa1 = packh2(s[2*kc  ][2], s[2*kc  ][3]);
                unsigned pa2 = packh2(s[2*kc+1][0], s[2*kc+1][1]);
                unsigned pa3 = packh2(s[2*kc+1][2], s[2*kc+1][3]);
                unsigned vb[8][2];
                #pragma unroll
                for (int ntp = 0; ntp < 4; ++ntp) {
                    unsigned ad = smem_u32(
                        &vs[(kc*16 + lr8 + lm1*8)*SKS2 + ntp*16 + lm2*8]);
                    ldsm_x4_t(vb[ntp*2][0], vb[ntp*2][1],
                              vb[ntp*2+1][0], vb[ntp*2+1][1], ad);
                }
                #pragma unroll
                for (int nt = 0; nt < 8; ++nt)
                    mma_f16(o[nt], pa0, pa1, pa2, pa3, vb[nt][0], vb[nt][1]);
            }
        }
    }

    // Store partials (fp16) + per-row m, l
    const size_t pbase = ((size_t)(b*NQ2 + i)*MAXC2 + c) * (QT*Dc);
    #pragma unroll
    for (int nt = 0; nt < 8; ++nt) {
        const int colb = nt*8 + 2*tg;
        *(unsigned*)&g_Op2h[pbase + (size_t)(w*16 + g    )*Dc + colb] =
            packh2(o[nt][0], o[nt][1]);
        *(unsigned*)&g_Op2h[pbase + (size_t)(w*16 + g + 8)*Dc + colb] =
            packh2(o[nt][2], o[nt][3]);
    }
    if (tg == 0) {
        const size_t rb = ((size_t)(b*NQ2 + i)*MAXC2 + c) * QT + w*16;
        g_m2[rb + g]     = m0v;  g_l2[rb + g]     = l0;
        g_m2[rb + g + 8] = m1v;  g_l2[rb + g + 8] = l1;
    }
}

// ---------------------------------------------------------------------------
// Kernel 3: combine fp16 split-KV partials. grid = (NQ2, B, 4), block 256.
// One uint4 (8 fp16 cols) per thread.
// ---------------------------------------------------------------------------
__global__ __launch_bounds__(256) void combine_kernel(float* __restrict__ out)
{
    const int i = blockIdx.x;
    const int b = blockIdx.y;
    const int nc = (2*(i+1) + SCH - 1) / SCH;
    const size_t cb = (size_t)(b*NQ2 + i) * MAXC2;

    const int f = blockIdx.z * 256 + threadIdx.x;   // [0, 1024): row*8grp
    const int row = f >> 3;
    const int grp = f & 7;

    float M = -1e30f;
    float mm[MAXC2];
    #pragma unroll
    for (int cc = 0; cc < MAXC2; ++cc) {
        if (cc < nc) {
            mm[cc] = g_m2[(cb + cc)*QT + row];
            M = fmaxf(M, mm[cc]);
        }
    }
    float L = 0.f;
    float o[8];
    #pragma unroll
    for (int q = 0; q < 8; ++q) o[q] = 0.f;
    #pragma unroll
    for (int cc = 0; cc < MAXC2; ++cc) {
        if (cc < nc) {
            float wgt = __expf(mm[cc] - M);
            L += wgt * g_l2[(cb + cc)*QT + row];
            uint4 p = *(const uint4*)&g_Op2h[(cb + cc)*(QT*Dc) + row*Dc + grp*8];
            float2 v0 = __half22float2(*(__half2*)&p.x);
            float2 v1 = __half22float2(*(__half2*)&p.y);
            float2 v2 = __half22float2(*(__half2*)&p.z);
            float2 v3 = __half22float2(*(__half2*)&p.w);
            o[0] += wgt*v0.x; o[1] += wgt*v0.y;
            o[2] += wgt*v1.x; o[3] += wgt*v1.y;
            o[4] += wgt*v2.x; o[5] += wgt*v2.y;
            o[6] += wgt*v3.x; o[7] += wgt*v3.y;
        }
    }
    float inv = 1.f / L;
    float4 o0, o1;
    o0.x = o[0]*inv; o0.y = o[1]*inv; o0.z = o[2]*inv; o0.w = o[3]*inv;
    o1.x = o[4]*inv; o1.y = o[5]*inv; o1.z = o[6]*inv; o1.w = o[7]*inv;
    float* dst = &out[((size_t)b*Tc + i*QT + row)*Dc + grp*8];
    *(float4*)dst       = o0;
    *(float4*)(dst + 4) = o1;
}

// ---------------------------------------------------------------------------
extern "C" void kernel_launch(void* const* d_in, const int* in_sizes, int n_in,
                              void* d_out, int out_size)
{
    const float* x  = (const float*)d_in[0];
    const float* Wq = (const float*)d_in[1];
    const float* bq = (const float*)d_in[2];
    const float* Wk = (const float*)d_in[3];
    const float* bk = (const float*)d_in[4];
    const float* Wv = (const float*)d_in[5];
    const float* bv = (const float*)d_in[6];
    float* out = (float*)d_out;

    prepx_kernel<<<(int)((size_t)BT*Cc/8/256), 256>>>(x);
    prepw_kernel<<<3*Dc*Cc/256, 256>>>(Wq, Wk, Wv);

    const int qkv_smem = 4*64*SA2 * (int)sizeof(__half);   // 36,864 B
    cudaFuncSetAttribute(qkv_kernel, cudaFuncAttributeMaxDynamicSharedMemorySize, qkv_smem);
    dim3 g1(BT/64, 3);
    qkv_kernel<<<g1, 128, qkv_smem>>>(bq, bk, bv);

    const int attn_smem = 4*64*SKS2 * (int)sizeof(__half); // 36,864 B
    cudaFuncSetAttribute(attn_kernel, cudaFuncAttributeMaxDynamicSharedMemorySize, attn_smem);
    dim3 g2(MAXC2, NQ2, Bc);
    attn_kernel<<<g2, 256, attn_smem>>>();

    dim3 g3(NQ2, Bc, 4);
    combine_kernel<<<g3, 256>>>(out);
}

// round 13
// speedup vs baseline: 1.1335x; 1.1335x over previous
#include <cuda_runtime.h>
#include <cuda_fp16.h>
#include <cstdint>

#define Bc 4
#define Tc 2048
#define Cc 1024
#define Dc 64
#define BT (Bc*Tc)

#define QT   128
#define NQ2  (Tc/QT)
#define SCH  4
#define MAXC2 8
#define SKS2 72            // attn K/V smem row stride in halves (144B)
#define SA2  40            // qkv smem row stride in halves (80B) -- R11 config
#define BKH  32            // qkv k-chunk in halves             -- R11 config

// Scratch (allocation-free rule => __device__ globals)
__device__ __half g_xh [(size_t)BT*Cc];              // fp16 x
__device__ __half g_WhT[3*Dc*Cc];                    // fp16 W^T [proj][n][k]
__device__ __half g_Qh [BT*Dc];                      // fp16 Q (pre-scaled)
__device__ __half g_Kh [BT*Dc];
__device__ __half g_Vh [BT*Dc];
__device__ __half g_Op2h[(size_t)Bc*NQ2*MAXC2*QT*Dc];   // fp16 partials
__device__ float  g_m2[Bc*NQ2*MAXC2*QT];
__device__ float  g_l2[Bc*NQ2*MAXC2*QT];

__device__ __forceinline__ unsigned packh2(float lo, float hi) {
    __half2 h = __floats2half2_rn(lo, hi);
    return *(unsigned*)&h;
}

__device__ __forceinline__ unsigned smem_u32(const void* p) {
    return (unsigned)__cvta_generic_to_shared(p);
}

__device__ __forceinline__ void mma_f16(float c[4], unsigned a0, unsigned a1,
                                        unsigned a2, unsigned a3,
                                        unsigned b0, unsigned b1) {
    asm volatile(
        "mma.sync.aligned.m16n8k16.row.col.f32.f16.f16.f32 "
        "{%0,%1,%2,%3}, {%4,%5,%6,%7}, {%8,%9}, {%0,%1,%2,%3};"
        : "+f"(c[0]), "+f"(c[1]), "+f"(c[2]), "+f"(c[3])
        : "r"(a0), "r"(a1), "r"(a2), "r"(a3), "r"(b0), "r"(b1));
}

__device__ __forceinline__ void ldsm_x4(unsigned& r0, unsigned& r1,
                                        unsigned& r2, unsigned& r3, unsigned a) {
    asm volatile("ldmatrix.sync.aligned.m8n8.x4.shared.b16 {%0,%1,%2,%3}, [%4];"
                 : "=r"(r0), "=r"(r1), "=r"(r2), "=r"(r3) : "r"(a));
}
__device__ __forceinline__ void ldsm_x4_t(unsigned& r0, unsigned& r1,
                                          unsigned& r2, unsigned& r3, unsigned a) {
    asm volatile("ldmatrix.sync.aligned.m8n8.x4.trans.shared.b16 {%0,%1,%2,%3}, [%4];"
                 : "=r"(r0), "=r"(r1), "=r"(r2), "=r"(r3) : "r"(a));
}

__device__ __forceinline__ void cp16(void* dst_smem, const void* src) {
    unsigned d = (unsigned)__cvta_generic_to_shared(dst_smem);
    asm volatile("cp.async.ca.shared.global [%0], [%1], 16;" :: "r"(d), "l"(src));
}
#define CP_COMMIT() asm volatile("cp.async.commit_group;")
#define CP_WAIT1()  asm volatile("cp.async.wait_group 1;")

// ---------------------------------------------------------------------------
// Kernel 0a: x -> fp16.  grid = 4096, block 256.
// ---------------------------------------------------------------------------
__global__ __launch_bounds__(256) void prepx_kernel(const float* __restrict__ x)
{
    size_t idx = (size_t)blockIdx.x * 256 + threadIdx.x;
    const float4* xg = (const float4*)x;
    float4 v0 = xg[2*idx], v1 = xg[2*idx + 1];
    __half2 h0 = __floats2half2_rn(v0.x, v0.y);
    __half2 h1 = __floats2half2_rn(v0.z, v0.w);
    __half2 h2 = __floats2half2_rn(v1.x, v1.y);
    __half2 h3 = __floats2half2_rn(v1.z, v1.w);
    uint4 o;
    o.x = *(unsigned*)&h0; o.y = *(unsigned*)&h1;
    o.z = *(unsigned*)&h2; o.w = *(unsigned*)&h3;
    ((uint4*)g_xh)[idx] = o;
}

// ---------------------------------------------------------------------------
// Kernel 0b: W^T -> fp16.  grid = 768, block 256.
// ---------------------------------------------------------------------------
__global__ __launch_bounds__(256) void prepw_kernel(
    const float* __restrict__ Wq, const float* __restrict__ Wk,
    const float* __restrict__ Wv)
{
    int e = blockIdx.x * 256 + threadIdx.x;
    int proj = e >> 16;
    int r = e & 65535;
    int k = r >> 6;
    int n = r & 63;
    const float* W = (proj == 0) ? Wq : (proj == 1) ? Wk : Wv;
    g_WhT[(size_t)proj*(Dc*Cc) + (size_t)n*Cc + k] = __float2half_rn(W[(size_t)k*Dc + n]);
}

// ---------------------------------------------------------------------------
// Kernel 1: QKV projection, fp16 m16n8k16 + ldmatrix, 2-stage cp.async.
// grid = (BT/64, 3), block = 128 (4 warps). Tile 64x64, k-chunk 32 halves.
// EXACT R11 configuration.
// ---------------------------------------------------------------------------
__global__ __launch_bounds__(128) void qkv_kernel(
    const float* __restrict__ bq, const float* __restrict__ bk,
    const float* __restrict__ bv)
{
    extern __shared__ __align__(16) __half sm[];
    __half* As = sm;                    // [2][64*SA2]
    __half* Bs = sm + 2*64*SA2;         // [2][64*SA2]

    const int tid = threadIdx.x;
    const int which = blockIdx.y;
    const __half* WT = g_WhT + (size_t)which * (Dc*Cc);
    const float* bias = (which == 0) ? bq : (which == 1) ? bk : bv;
    __half* O = (which == 0) ? g_Qh : (which == 1) ? g_Kh : g_Vh;
    const float osc = (which == 0) ? 0.125f : 1.0f;

    const int m0 = blockIdx.x * 64;
    const int w  = tid >> 5;
    const int lane = tid & 31;
    const int g  = lane >> 2;
    const int tg = lane & 3;
    const int wm = (w & 1) * 32;
    const int wn = (w >> 1) * 32;

    const int lr8 = lane & 7;
    const int lm1 = (lane >> 3) & 1;
    const int lm2 = lane >> 4;

    const int l_row = tid >> 2, l_c16 = tid & 3;

    float acc[2][4][4];
    #pragma unroll
    for (int mt = 0; mt < 2; ++mt)
        #pragma unroll
        for (int nt = 0; nt < 4; ++nt)
            #pragma unroll
            for (int q = 0; q < 4; ++q) acc[mt][nt][q] = 0.f;

    // Prologue: stage kc=0
    {
        #pragma unroll
        for (int j = 0; j < 2; ++j) {
            int row = l_row + 32*j;
            cp16(&As[row*SA2 + l_c16*8], &g_xh[(size_t)(m0 + row)*Cc + l_c16*8]);
            cp16(&Bs[row*SA2 + l_c16*8], &WT[(size_t)row*Cc + l_c16*8]);
        }
        CP_COMMIT();
    }

    const int NIT = Cc / BKH;            // 32
    for (int kc = 0; kc < NIT; ++kc) {
        const int buf = kc & 1;
        __half* Ab = As + buf*64*SA2;
        __half* Bb = Bs + buf*64*SA2;
        __half* An = As + (buf^1)*64*SA2;
        __half* Bn = Bs + (buf^1)*64*SA2;

        __syncthreads();
        if (kc + 1 < NIT) {
            #pragma unroll
            for (int j = 0; j < 2; ++j) {
                int row = l_row + 32*j;
                cp16(&An[row*SA2 + l_c16*8],
                     &g_xh[(size_t)(m0 + row)*Cc + (kc+1)*BKH + l_c16*8]);
                cp16(&Bn[row*SA2 + l_c16*8],
                     &WT[(size_t)row*Cc + (kc+1)*BKH + l_c16*8]);
            }
        }
        CP_COMMIT();
        CP_WAIT1();
        __syncthreads();

        #pragma unroll
        for (int ks = 0; ks < 2; ++ks) {
            const int k0 = ks * 16;
            unsigned a[2][4], b[4][2];
            #pragma unroll
            for (int mt = 0; mt < 2; ++mt) {
                unsigned ad = smem_u32(
                    &Ab[(wm + mt*16 + lr8 + lm1*8)*SA2 + k0 + lm2*8]);
                ldsm_x4(a[mt][0], a[mt][1], a[mt][2], a[mt][3], ad);
            }
            #pragma unroll
            for (int ntp = 0; ntp < 2; ++ntp) {
                unsigned bd = smem_u32(
                    &Bb[(wn + ntp*16 + lr8 + lm2*8)*SA2 + k0 + lm1*8]);
                ldsm_x4(b[ntp*2][0], b[ntp*2][1], b[ntp*2+1][0], b[ntp*2+1][1], bd);
            }
            #pragma unroll
            for (int mt = 0; mt < 2; ++mt)
                #pragma unroll
                for (int nt = 0; nt < 4; ++nt)
                    mma_f16(acc[mt][nt], a[mt][0], a[mt][1], a[mt][2], a[mt][3],
                            b[nt][0], b[nt][1]);
        }
    }

    // Writeback fp16 (Q scaled by 1/8)
    #pragma unroll
    for (int nt = 0; nt < 4; ++nt) {
        const int col = wn + nt*8 + 2*tg;
        float bx = bias[col], by = bias[col+1];
        #pragma unroll
        for (int mt = 0; mt < 2; ++mt) {
            int row = m0 + wm + mt*16 + g;
            __half2 h0 = __floats2half2_rn((acc[mt][nt][0]+bx)*osc, (acc[mt][nt][1]+by)*osc);
            __half2 h1 = __floats2half2_rn((acc[mt][nt][2]+bx)*osc, (acc[mt][nt][3]+by)*osc);
            *(__half2*)&O[(size_t)row*Dc + col]     = h0;
            *(__half2*)&O[(size_t)(row+8)*Dc + col] = h1;
        }
    }
}

// ---------------------------------------------------------------------------
// Kernel 2: fp16 m16n8k16 flash attention, split-KV, cp.async + ldmatrix.
// grid = (MAXC2, NQ2, B), block = 256 (8 warps). fp16 partial output.
// ---------------------------------------------------------------------------
__global__ __launch_bounds__(256, 2) void attn_kernel()
{
    const int c = blockIdx.x;
    const int i = blockIdx.y;
    const int b = blockIdx.z;
    const int ktot = 2*(i+1);
    const int kt0 = c * SCH;
    if (kt0 >= ktot) return;
    const int kt1 = min(kt0 + SCH, ktot);

    extern __shared__ __align__(16) __half smem[];
    __half* Ksm = smem;                  // [2][64*SKS2]
    __half* Vsm = smem + 2*64*SKS2;      // [2][64*SKS2]

    const int tid = threadIdx.x;
    const int w = tid >> 5, lane = tid & 31;
    const int g = lane >> 2, tg = lane & 3;
    const int qrow = i*QT + w*16;
    const size_t bT = (size_t)b * Tc;

    const int lr8 = lane & 7;
    const int lm1 = (lane >> 3) & 1;
    const int lm2 = lane >> 4;

    const int l_row = tid >> 2;          // 0..63
    const int l_c16 = tid & 3;           // 0..3

    // Prologue: stage tile kt0
    {
        const __half* Kg = &g_Kh[(bT + kt0*64 + l_row)*Dc];
        const __half* Vg = &g_Vh[(bT + kt0*64 + l_row)*Dc];
        cp16(&Ksm[l_row*SKS2 + l_c16*8],      Kg + l_c16*8);
        cp16(&Ksm[l_row*SKS2 + 32 + l_c16*8], Kg + 32 + l_c16*8);
        cp16(&Vsm[l_row*SKS2 + l_c16*8],      Vg + l_c16*8);
        cp16(&Vsm[l_row*SKS2 + 32 + l_c16*8], Vg + 32 + l_c16*8);
        CP_COMMIT();
    }

    // Q A-fragments
    unsigned qa[4][4];
    {
        const __half* Qp = &g_Qh[(bT + qrow)*Dc];
        #pragma unroll
        for (int kc = 0; kc < 4; ++kc) {
            qa[kc][0] = *(const unsigned*)&Qp[(g  )*Dc + kc*16 + 2*tg];
            qa[kc][1] = *(const unsigned*)&Qp[(g+8)*Dc + kc*16 + 2*tg];
            qa[kc][2] = *(const unsigned*)&Qp[(g  )*Dc + kc*16 + 8 + 2*tg];
            qa[kc][3] = *(const unsigned*)&Qp[(g+8)*Dc + kc*16 + 8 + 2*tg];
        }
    }

    float o[8][4];
    #pragma unroll
    for (int nt = 0; nt < 8; ++nt)
        #pragma unroll
        for (int q = 0; q < 4; ++q) o[nt][q] = 0.f;
    float m0v = -1e30f, m1v = -1e30f, l0 = 0.f, l1 = 0.f;

    for (int kt = kt0; kt < kt1; ++kt) {
        const int buf = (kt - kt0) & 1;
        const __half* ks = Ksm + buf*64*SKS2;
        const __half* vs = Vsm + buf*64*SKS2;
        __half* kn = Ksm + (buf^1)*64*SKS2;
        __half* vn = Vsm + (buf^1)*64*SKS2;

        __syncthreads();
        if (kt + 1 < kt1) {
            const __half* Kg = &g_Kh[(bT + (kt+1)*64 + l_row)*Dc];
            const __half* Vg = &g_Vh[(bT + (kt+1)*64 + l_row)*Dc];
            cp16(&kn[l_row*SKS2 + l_c16*8],      Kg + l_c16*8);
            cp16(&kn[l_row*SKS2 + 32 + l_c16*8], Kg + 32 + l_c16*8);
            cp16(&vn[l_row*SKS2 + l_c16*8],      Vg + l_c16*8);
            cp16(&vn[l_row*SKS2 + 32 + l_c16*8], Vg + 32 + l_c16*8);
        }
        CP_COMMIT();
        CP_WAIT1();
        __syncthreads();

        const int kb = kt * 64;
        if (kb <= qrow + 15) {
            // --- S = Q @ K^T ---
            float s[8][4];
            #pragma unroll
            for (int nt = 0; nt < 8; ++nt)
                { s[nt][0]=0.f; s[nt][1]=0.f; s[nt][2]=0.f; s[nt][3]=0.f; }
            #pragma unroll
            for (int kc = 0; kc < 4; ++kc) {
                unsigned kb_[8][2];
                #pragma unroll
                for (int ntp = 0; ntp < 4; ++ntp) {
                    unsigned ad = smem_u32(
                        &ks[(ntp*16 + lr8 + lm2*8)*SKS2 + kc*16 + lm1*8]);
                    ldsm_x4(kb_[ntp*2][0], kb_[ntp*2][1],
                            kb_[ntp*2+1][0], kb_[ntp*2+1][1], ad);
                }
                #pragma unroll
                for (int nt = 0; nt < 8; ++nt)
                    mma_f16(s[nt], qa[kc][0], qa[kc][1], qa[kc][2], qa[kc][3],
                            kb_[nt][0], kb_[nt][1]);
            }

            // --- causal mask ---
            if (kb + 63 > qrow) {
                const int r0 = qrow + g, r1 = r0 + 8;
                #pragma unroll
                for (int nt = 0; nt < 8; ++nt) {
                    int col = kb + nt*8 + 2*tg;
                    if (col   > r0) s[nt][0] = -1e30f;
                    if (col+1 > r0) s[nt][1] = -1e30f;
                    if (col   > r1) s[nt][2] = -1e30f;
                    if (col+1 > r1) s[nt][3] = -1e30f;
                }
            }

            // --- online softmax ---
            float rm0 = -1e30f, rm1 = -1e30f;
            #pragma unroll
            for (int nt = 0; nt < 8; ++nt) {
                rm0 = fmaxf(rm0, fmaxf(s[nt][0], s[nt][1]));
                rm1 = fmaxf(rm1, fmaxf(s[nt][2], s[nt][3]));
            }
            rm0 = fmaxf(rm0, __shfl_xor_sync(0xffffffffu, rm0, 1));
            rm0 = fmaxf(rm0, __shfl_xor_sync(0xffffffffu, rm0, 2));
            rm1 = fmaxf(rm1, __shfl_xor_sync(0xffffffffu, rm1, 1));
            rm1 = fmaxf(rm1, __shfl_xor_sync(0xffffffffu, rm1, 2));
            const float mn0 = fmaxf(m0v, rm0), mn1 = fmaxf(m1v, rm1);
            const float f0 = __expf(m0v - mn0), f1 = __expf(m1v - mn1);
            m0v = mn0; m1v = mn1;

            float rs0 = 0.f, rs1 = 0.f;
            #pragma unroll
            for (int nt = 0; nt < 8; ++nt) {
                s[nt][0] = __expf(s[nt][0] - mn0);
                s[nt][1] = __expf(s[nt][1] - mn0);
                s[nt][2] = __expf(s[nt][2] - mn1);
                s[nt][3] = __expf(s[nt][3] - mn1);
                rs0 += s[nt][0] + s[nt][1];
                rs1 += s[nt][2] + s[nt][3];
            }
            rs0 += __shfl_xor_sync(0xffffffffu, rs0, 1);
            rs0 += __shfl_xor_sync(0xffffffffu, rs0, 2);
            rs1 += __shfl_xor_sync(0xffffffffu, rs1, 1);
            rs1 += __shfl_xor_sync(0xffffffffu, rs1, 2);
            l0 = l0*f0 + rs0;
            l1 = l1*f1 + rs1;
            #pragma unroll
            for (int nt = 0; nt < 8; ++nt) {
                o[nt][0] *= f0; o[nt][1] *= f0;
                o[nt][2] *= f1; o[nt][3] *= f1;
            }

            // --- O += P @ V ---
            #pragma unroll
            for (int kc = 0; kc < 4; ++kc) {
                unsigned pa0 = packh2(s[2*kc  ][0], s[2*kc  ][1]);
                unsigned pa1 = packh2(s[2*kc  ][2], s[2*kc  ][3]);
                unsigned pa2 = packh2(s[2*kc+1][0], s[2*kc+1][1]);
                unsigned pa3 = packh2(s[2*kc+1][2], s[2*kc+1][3]);
                unsigned vb[8][2];
                #pragma unroll
                for (int ntp = 0; ntp < 4; ++ntp) {
                    unsigned ad = smem_u32(
                        &vs[(kc*16 + lr8 + lm1*8)*SKS2 + ntp*16 + lm2*8]);
                    ldsm_x4_t(vb[ntp*2][0], vb[ntp*2][1],
                              vb[ntp*2+1][0], vb[ntp*2+1][1], ad);
                }
                #pragma unroll
                for (int nt = 0; nt < 8; ++nt)
                    mma_f16(o[nt], pa0, pa1, pa2, pa3, vb[nt][0], vb[nt][1]);
            }
        }
    }

    // Store partials (fp16) + per-row m, l
    const size_t pbase = ((size_t)(b*NQ2 + i)*MAXC2 + c) * (QT*Dc);
    #pragma unroll
    for (int nt = 0; nt < 8; ++nt) {
        const int colb = nt*8 + 2*tg;
        *(unsigned*)&g_Op2h[pbase + (size_t)(w*16 + g    )*Dc + colb] =
            packh2(o[nt][0], o[nt][1]);
        *(unsigned*)&g_Op2h[pbase + (size_t)(w*16 + g + 8)*Dc + colb] =
            packh2(o[nt][2], o[nt][3]);
    }
    if (tg == 0) {
        const size_t rb = ((size_t)(b*NQ2 + i)*MAXC2 + c) * QT + w*16;
        g_m2[rb + g]     = m0v;  g_l2[rb + g]     = l0;
        g_m2[rb + g + 8] = m1v;  g_l2[rb + g + 8] = l1;
    }
}

// ---------------------------------------------------------------------------
// Kernel 3: combine fp16 split-KV partials. grid = (NQ2, B, 4), block 256.
// One uint4 (8 fp16 cols) per thread.
// ---------------------------------------------------------------------------
__global__ __launch_bounds__(256) void combine_kernel(float* __restrict__ out)
{
    const int i = blockIdx.x;
    const int b = blockIdx.y;
    const int nc = (2*(i+1) + SCH - 1) / SCH;
    const size_t cb = (size_t)(b*NQ2 + i) * MAXC2;

    const int f = blockIdx.z * 256 + threadIdx.x;   // [0, 1024)
    const int row = f >> 3;
    const int grp = f & 7;

    float M = -1e30f;
    float mm[MAXC2];
    #pragma unroll
    for (int cc = 0; cc < MAXC2; ++cc) {
        if (cc < nc) {
            mm[cc] = g_m2[(cb + cc)*QT + row];
            M = fmaxf(M, mm[cc]);
        }
    }
    float L = 0.f;
    float o[8];
    #pragma unroll
    for (int q = 0; q < 8; ++q) o[q] = 0.f;
    #pragma unroll
    for (int cc = 0; cc < MAXC2; ++cc) {
        if (cc < nc) {
            float wgt = __expf(mm[cc] - M);
            L += wgt * g_l2[(cb + cc)*QT + row];
            uint4 p = *(const uint4*)&g_Op2h[(cb + cc)*(QT*Dc) + row*Dc + grp*8];
            float2 v0 = __half22float2(*(__half2*)&p.x);
            float2 v1 = __half22float2(*(__half2*)&p.y);
            float2 v2 = __half22float2(*(__half2*)&p.z);
            float2 v3 = __half22float2(*(__half2*)&p.w);
            o[0] += wgt*v0.x; o[1] += wgt*v0.y;
            o[2] += wgt*v1.x; o[3] += wgt*v1.y;
            o[4] += wgt*v2.x; o[5] += wgt*v2.y;
            o[6] += wgt*v3.x; o[7] += wgt*v3.y;
        }
    }
    float inv = 1.f / L;
    float4 o0, o1;
    o0.x = o[0]*inv; o0.y = o[1]*inv; o0.z = o[2]*inv; o0.w = o[3]*inv;
    o1.x = o[4]*inv; o1.y = o[5]*inv; o1.z = o[6]*inv; o1.w = o[7]*inv;
    float* dst = &out[((size_t)b*Tc + i*QT + row)*Dc + grp*8];
    *(float4*)dst       = o0;
    *(float4*)(dst + 4) = o1;
}

// ---------------------------------------------------------------------------
extern "C" void kernel_launch(void* const* d_in, const int* in_sizes, int n_in,
                              void* d_out, int out_size)
{
    const float* x  = (const float*)d_in[0];
    const float* Wq = (const float*)d_in[1];
    const float* bq = (const float*)d_in[2];
    const float* Wk = (const float*)d_in[3];
    const float* bk = (const float*)d_in[4];
    const float* Wv = (const float*)d_in[5];
    const float* bv = (const float*)d_in[6];
    float* out = (float*)d_out;

    prepx_kernel<<<(int)((size_t)BT*Cc/8/256), 256>>>(x);
    prepw_kernel<<<3*Dc*Cc/256, 256>>>(Wq, Wk, Wv);

    const int qkv_smem = 4*64*SA2 * (int)sizeof(__half);   // 20,480 B (R11)
    cudaFuncSetAttribute(qkv_kernel, cudaFuncAttributeMaxDynamicSharedMemorySize, qkv_smem);
    dim3 g1(BT/64, 3);
    qkv_kernel<<<g1, 128, qkv_smem>>>(bq, bk, bv);

    const int attn_smem = 4*64*SKS2 * (int)sizeof(__half); // 36,864 B
    cudaFuncSetAttribute(attn_kernel, cudaFuncAttributeMaxDynamicSharedMemorySize, attn_smem);
    dim3 g2(MAXC2, NQ2, Bc);
    attn_kernel<<<g2, 256, attn_smem>>>();

    dim3 g3(NQ2, Bc, 4);
    combine_kernel<<<g3, 256>>>(out);
}

// round 14
// speedup vs baseline: 1.2354x; 1.0900x over previous
#include <cuda_runtime.h>
#include <cuda_fp16.h>
#include <cstdint>

#define Bc 4
#define Tc 2048
#define Cc 1024
#define Dc 64
#define BT (Bc*Tc)

#define QT   128
#define NQ2  (Tc/QT)
#define SCH  4
#define MAXC2 8
#define SKS2 72            // attn K/V smem row stride in halves (144B)
#define SA2  40            // qkv smem row stride in halves (80B)
#define BKH  32            // qkv k-chunk in halves

// Scratch (allocation-free rule => __device__ globals)
__device__ __half g_xh [(size_t)BT*Cc];              // fp16 x
__device__ __half g_WhT[3*Dc*Cc];                    // fp16 W^T [proj][n][k]
__device__ __half g_Qh [BT*Dc];                      // fp16 Q (pre-scaled)
__device__ __half g_Kh [BT*Dc];
__device__ __half g_Vh [BT*Dc];
__device__ __half g_Op2h[(size_t)Bc*NQ2*MAXC2*QT*Dc];   // fp16 partials
__device__ float  g_m2[Bc*NQ2*MAXC2*QT];
__device__ float  g_l2[Bc*NQ2*MAXC2*QT];

__device__ __forceinline__ unsigned packh2(float lo, float hi) {
    __half2 h = __floats2half2_rn(lo, hi);
    return *(unsigned*)&h;
}

__device__ __forceinline__ unsigned smem_u32(const void* p) {
    return (unsigned)__cvta_generic_to_shared(p);
}

__device__ __forceinline__ void mma_f16(float c[4], unsigned a0, unsigned a1,
                                        unsigned a2, unsigned a3,
                                        unsigned b0, unsigned b1) {
    asm volatile(
        "mma.sync.aligned.m16n8k16.row.col.f32.f16.f16.f32 "
        "{%0,%1,%2,%3}, {%4,%5,%6,%7}, {%8,%9}, {%0,%1,%2,%3};"
        : "+f"(c[0]), "+f"(c[1]), "+f"(c[2]), "+f"(c[3])
        : "r"(a0), "r"(a1), "r"(a2), "r"(a3), "r"(b0), "r"(b1));
}

__device__ __forceinline__ void ldsm_x4(unsigned& r0, unsigned& r1,
                                        unsigned& r2, unsigned& r3, unsigned a) {
    asm volatile("ldmatrix.sync.aligned.m8n8.x4.shared.b16 {%0,%1,%2,%3}, [%4];"
                 : "=r"(r0), "=r"(r1), "=r"(r2), "=r"(r3) : "r"(a));
}
__device__ __forceinline__ void ldsm_x4_t(unsigned& r0, unsigned& r1,
                                          unsigned& r2, unsigned& r3, unsigned a) {
    asm volatile("ldmatrix.sync.aligned.m8n8.x4.trans.shared.b16 {%0,%1,%2,%3}, [%4];"
                 : "=r"(r0), "=r"(r1), "=r"(r2), "=r"(r3) : "r"(a));
}

__device__ __forceinline__ void cp16(void* dst_smem, const void* src) {
    unsigned d = (unsigned)__cvta_generic_to_shared(dst_smem);
    asm volatile("cp.async.ca.shared.global [%0], [%1], 16;" :: "r"(d), "l"(src));
}
#define CP_COMMIT() asm volatile("cp.async.commit_group;")
#define CP_WAIT1()  asm volatile("cp.async.wait_group 1;")

// ---------------------------------------------------------------------------
// Kernel 0: fused prep. blocks [0,4096): x -> fp16; [4096,4864): W^T -> fp16.
// ---------------------------------------------------------------------------
__global__ __launch_bounds__(256) void prep_kernel(
    const float* __restrict__ x,
    const float* __restrict__ Wq, const float* __restrict__ Wk,
    const float* __restrict__ Wv)
{
    if (blockIdx.x < 4096) {
        size_t idx = (size_t)blockIdx.x * 256 + threadIdx.x;   // 8 halves/thread
        const float4* xg = (const float4*)x;
        float4 v0 = xg[2*idx], v1 = xg[2*idx + 1];
        __half2 h0 = __floats2half2_rn(v0.x, v0.y);
        __half2 h1 = __floats2half2_rn(v0.z, v0.w);
        __half2 h2 = __floats2half2_rn(v1.x, v1.y);
        __half2 h3 = __floats2half2_rn(v1.z, v1.w);
        uint4 o;
        o.x = *(unsigned*)&h0; o.y = *(unsigned*)&h1;
        o.z = *(unsigned*)&h2; o.w = *(unsigned*)&h3;
        ((uint4*)g_xh)[idx] = o;
    } else {
        int e = (blockIdx.x - 4096) * 256 + threadIdx.x;
        int proj = e >> 16;
        int r = e & 65535;
        int k = r >> 6;
        int n = r & 63;
        const float* W = (proj == 0) ? Wq : (proj == 1) ? Wk : Wv;
        g_WhT[(size_t)proj*(Dc*Cc) + (size_t)n*Cc + k] =
            __float2half_rn(W[(size_t)k*Dc + n]);
    }
}

// ---------------------------------------------------------------------------
// Kernel 1: QKV projection, fp16 m16n8k16 + ldmatrix, 2-stage cp.async.
// grid = (BT/64, 3), block = 128 (4 warps). Tile 64x64, k-chunk 32. (R11)
// ---------------------------------------------------------------------------
__global__ __launch_bounds__(128) void qkv_kernel(
    const float* __restrict__ bq, const float* __restrict__ bk,
    const float* __restrict__ bv)
{
    extern __shared__ __align__(16) __half sm[];
    __half* As = sm;                    // [2][64*SA2]
    __half* Bs = sm + 2*64*SA2;         // [2][64*SA2]

    const int tid = threadIdx.x;
    const int which = blockIdx.y;
    const __half* WT = g_WhT + (size_t)which * (Dc*Cc);
    const float* bias = (which == 0) ? bq : (which == 1) ? bk : bv;
    __half* O = (which == 0) ? g_Qh : (which == 1) ? g_Kh : g_Vh;
    const float osc = (which == 0) ? 0.125f : 1.0f;

    const int m0 = blockIdx.x * 64;
    const int w  = tid >> 5;
    const int lane = tid & 31;
    const int g  = lane >> 2;
    const int tg = lane & 3;
    const int wm = (w & 1) * 32;
    const int wn = (w >> 1) * 32;

    const int lr8 = lane & 7;
    const int lm1 = (lane >> 3) & 1;
    const int lm2 = lane >> 4;

    const int l_row = tid >> 2, l_c16 = tid & 3;

    float acc[2][4][4];
    #pragma unroll
    for (int mt = 0; mt < 2; ++mt)
        #pragma unroll
        for (int nt = 0; nt < 4; ++nt)
            #pragma unroll
            for (int q = 0; q < 4; ++q) acc[mt][nt][q] = 0.f;

    // Prologue: stage kc=0
    {
        #pragma unroll
        for (int j = 0; j < 2; ++j) {
            int row = l_row + 32*j;
            cp16(&As[row*SA2 + l_c16*8], &g_xh[(size_t)(m0 + row)*Cc + l_c16*8]);
            cp16(&Bs[row*SA2 + l_c16*8], &WT[(size_t)row*Cc + l_c16*8]);
        }
        CP_COMMIT();
    }

    const int NIT = Cc / BKH;            // 32
    for (int kc = 0; kc < NIT; ++kc) {
        const int buf = kc & 1;
        __half* Ab = As + buf*64*SA2;
        __half* Bb = Bs + buf*64*SA2;
        __half* An = As + (buf^1)*64*SA2;
        __half* Bn = Bs + (buf^1)*64*SA2;

        __syncthreads();
        if (kc + 1 < NIT) {
            #pragma unroll
            for (int j = 0; j < 2; ++j) {
                int row = l_row + 32*j;
                cp16(&An[row*SA2 + l_c16*8],
                     &g_xh[(size_t)(m0 + row)*Cc + (kc+1)*BKH + l_c16*8]);
                cp16(&Bn[row*SA2 + l_c16*8],
                     &WT[(size_t)row*Cc + (kc+1)*BKH + l_c16*8]);
            }
        }
        CP_COMMIT();
        CP_WAIT1();
        __syncthreads();

        #pragma unroll
        for (int ks = 0; ks < 2; ++ks) {
            const int k0 = ks * 16;
            unsigned a[2][4], b[4][2];
            #pragma unroll
            for (int mt = 0; mt < 2; ++mt) {
                unsigned ad = smem_u32(
                    &Ab[(wm + mt*16 + lr8 + lm1*8)*SA2 + k0 + lm2*8]);
                ldsm_x4(a[mt][0], a[mt][1], a[mt][2], a[mt][3], ad);
            }
            #pragma unroll
            for (int ntp = 0; ntp < 2; ++ntp) {
                unsigned bd = smem_u32(
                    &Bb[(wn + ntp*16 + lr8 + lm2*8)*SA2 + k0 + lm1*8]);
                ldsm_x4(b[ntp*2][0], b[ntp*2][1], b[ntp*2+1][0], b[ntp*2+1][1], bd);
            }
            #pragma unroll
            for (int mt = 0; mt < 2; ++mt)
                #pragma unroll
                for (int nt = 0; nt < 4; ++nt)
                    mma_f16(acc[mt][nt], a[mt][0], a[mt][1], a[mt][2], a[mt][3],
                            b[nt][0], b[nt][1]);
        }
    }

    // Writeback fp16 (Q scaled by 1/8)
    #pragma unroll
    for (int nt = 0; nt < 4; ++nt) {
        const int col = wn + nt*8 + 2*tg;
        float bx = bias[col], by = bias[col+1];
        #pragma unroll
        for (int mt = 0; mt < 2; ++mt) {
            int row = m0 + wm + mt*16 + g;
            __half2 h0 = __floats2half2_rn((acc[mt][nt][0]+bx)*osc, (acc[mt][nt][1]+by)*osc);
            __half2 h1 = __floats2half2_rn((acc[mt][nt][2]+bx)*osc, (acc[mt][nt][3]+by)*osc);
            *(__half2*)&O[(size_t)row*Dc + col]     = h0;
            *(__half2*)&O[(size_t)(row+8)*Dc + col] = h1;
        }
    }
}

// ---------------------------------------------------------------------------
// Kernel 2: fp16 m16n8k16 flash attention, split-KV, cp.async + ldmatrix.
// grid = (MAXC2, NQ2, B), block = 256 (8 warps). fp16 partial output.
// ---------------------------------------------------------------------------
__global__ __launch_bounds__(256, 2) void attn_kernel()
{
    const int c = blockIdx.x;
    const int i = blockIdx.y;
    const int b = blockIdx.z;
    const int ktot = 2*(i+1);
    const int kt0 = c * SCH;
    if (kt0 >= ktot) return;
    const int kt1 = min(kt0 + SCH, ktot);

    extern __shared__ __align__(16) __half smem[];
    __half* Ksm = smem;                  // [2][64*SKS2]
    __half* Vsm = smem + 2*64*SKS2;      // [2][64*SKS2]

    const int tid = threadIdx.x;
    const int w = tid >> 5, lane = tid & 31;
    const int g = lane >> 2, tg = lane & 3;
    const int qrow = i*QT + w*16;
    const size_t bT = (size_t)b * Tc;

    const int lr8 = lane & 7;
    const int lm1 = (lane >> 3) & 1;
    const int lm2 = lane >> 4;

    const int l_row = tid >> 2;          // 0..63
    const int l_c16 = tid & 3;           // 0..3

    // Prologue: stage tile kt0
    {
        const __half* Kg = &g_Kh[(bT + kt0*64 + l_row)*Dc];
        const __half* Vg = &g_Vh[(bT + kt0*64 + l_row)*Dc];
        cp16(&Ksm[l_row*SKS2 + l_c16*8],      Kg + l_c16*8);
        cp16(&Ksm[l_row*SKS2 + 32 + l_c16*8], Kg + 32 + l_c16*8);
        cp16(&Vsm[l_row*SKS2 + l_c16*8],      Vg + l_c16*8);
        cp16(&Vsm[l_row*SKS2 + 32 + l_c16*8], Vg + 32 + l_c16*8);
        CP_COMMIT();
    }

    // Q A-fragments
    unsigned qa[4][4];
    {
        const __half* Qp = &g_Qh[(bT + qrow)*Dc];
        #pragma unroll
        for (int kc = 0; kc < 4; ++kc) {
            qa[kc][0] = *(const unsigned*)&Qp[(g  )*Dc + kc*16 + 2*tg];
            qa[kc][1] = *(const unsigned*)&Qp[(g+8)*Dc + kc*16 + 2*tg];
            qa[kc][2] = *(const unsigned*)&Qp[(g  )*Dc + kc*16 + 8 + 2*tg];
            qa[kc][3] = *(const unsigned*)&Qp[(g+8)*Dc + kc*16 + 8 + 2*tg];
        }
    }

    float o[8][4];
    #pragma unroll
    for (int nt = 0; nt < 8; ++nt)
        #pragma unroll
        for (int q = 0; q < 4; ++q) o[nt][q] = 0.f;
    float m0v = -1e30f, m1v = -1e30f, l0 = 0.f, l1 = 0.f;

    for (int kt = kt0; kt < kt1; ++kt) {
        const int buf = (kt - kt0) & 1;
        const __half* ks = Ksm + buf*64*SKS2;
        const __half* vs = Vsm + buf*64*SKS2;
        __half* kn = Ksm + (buf^1)*64*SKS2;
        __half* vn = Vsm + (buf^1)*64*SKS2;

        __syncthreads();
        if (kt + 1 < kt1) {
            const __half* Kg = &g_Kh[(bT + (kt+1)*64 + l_row)*Dc];
            const __half* Vg = &g_Vh[(bT + (kt+1)*64 + l_row)*Dc];
            cp16(&kn[l_row*SKS2 + l_c16*8],      Kg + l_c16*8);
            cp16(&kn[l_row*SKS2 + 32 + l_c16*8], Kg + 32 + l_c16*8);
            cp16(&vn[l_row*SKS2 + l_c16*8],      Vg + l_c16*8);
            cp16(&vn[l_row*SKS2 + 32 + l_c16*8], Vg + 32 + l_c16*8);
        }
        CP_COMMIT();
        CP_WAIT1();
        __syncthreads();

        const int kb = kt * 64;
        if (kb <= qrow + 15) {
            // --- S = Q @ K^T ---
            float s[8][4];
            #pragma unroll
            for (int nt = 0; nt < 8; ++nt)
                { s[nt][0]=0.f; s[nt][1]=0.f; s[nt][2]=0.f; s[nt][3]=0.f; }
            #pragma unroll
            for (int kc = 0; kc < 4; ++kc) {
                unsigned kb_[8][2];
                #pragma unroll
                for (int ntp = 0; ntp < 4; ++ntp) {
                    unsigned ad = smem_u32(
                        &ks[(ntp*16 + lr8 + lm2*8)*SKS2 + kc*16 + lm1*8]);
                    ldsm_x4(kb_[ntp*2][0], kb_[ntp*2][1],
                            kb_[ntp*2+1][0], kb_[ntp*2+1][1], ad);
                }
                #pragma unroll
                for (int nt = 0; nt < 8; ++nt)
                    mma_f16(s[nt], qa[kc][0], qa[kc][1], qa[kc][2], qa[kc][3],
                            kb_[nt][0], kb_[nt][1]);
            }

            // --- causal mask ---
            if (kb + 63 > qrow) {
                const int r0 = qrow + g, r1 = r0 + 8;
                #pragma unroll
                for (int nt = 0; nt < 8; ++nt) {
                    int col = kb + nt*8 + 2*tg;
                    if (col   > r0) s[nt][0] = -1e30f;
                    if (col+1 > r0) s[nt][1] = -1e30f;
                    if (col   > r1) s[nt][2] = -1e30f;
                    if (col+1 > r1) s[nt][3] = -1e30f;
                }
            }

            // --- online softmax ---
            float rm0 = -1e30f, rm1 = -1e30f;
            #pragma unroll
            for (int nt = 0; nt < 8; ++nt) {
                rm0 = fmaxf(rm0, fmaxf(s[nt][0], s[nt][1]));
                rm1 = fmaxf(rm1, fmaxf(s[nt][2], s[nt][3]));
            }
            rm0 = fmaxf(rm0, __shfl_xor_sync(0xffffffffu, rm0, 1));
            rm0 = fmaxf(rm0, __shfl_xor_sync(0xffffffffu, rm0, 2));
            rm1 = fmaxf(rm1, __shfl_xor_sync(0xffffffffu, rm1, 1));
            rm1 = fmaxf(rm1, __shfl_xor_sync(0xffffffffu, rm1, 2));
            const float mn0 = fmaxf(m0v, rm0), mn1 = fmaxf(m1v, rm1);
            const float f0 = __expf(m0v - mn0), f1 = __expf(m1v - mn1);
            m0v = mn0; m1v = mn1;

            float rs0 = 0.f, rs1 = 0.f;
            #pragma unroll
            for (int nt = 0; nt < 8; ++nt) {
                s[nt][0] = __expf(s[nt][0] - mn0);
                s[nt][1] = __expf(s[nt][1] - mn0);
                s[nt][2] = __expf(s[nt][2] - mn1);
                s[nt][3] = __expf(s[nt][3] - mn1);
                rs0 += s[nt][0] + s[nt][1];
                rs1 += s[nt][2] + s[nt][3];
            }
            rs0 += __shfl_xor_sync(0xffffffffu, rs0, 1);
            rs0 += __shfl_xor_sync(0xffffffffu, rs0, 2);
            rs1 += __shfl_xor_sync(0xffffffffu, rs1, 1);
            rs1 += __shfl_xor_sync(0xffffffffu, rs1, 2);
            l0 = l0*f0 + rs0;
            l1 = l1*f1 + rs1;
            #pragma unroll
            for (int nt = 0; nt < 8; ++nt) {
                o[nt][0] *= f0; o[nt][1] *= f0;
                o[nt][2] *= f1; o[nt][3] *= f1;
            }

            // --- O += P @ V ---
            #pragma unroll
            for (int kc = 0; kc < 4; ++kc) {
                unsigned pa0 = packh2(s[2*kc  ][0], s[2*kc  ][1]);
                unsigned pa1 = packh2(s[2*kc  ][2], s[2*kc  ][3]);
                unsigned pa2 = packh2(s[2*kc+1][0], s[2*kc+1][1]);
                unsigned pa3 = packh2(s[2*kc+1][2], s[2*kc+1][3]);
                unsigned vb[8][2];
                #pragma unroll
                for (int ntp = 0; ntp < 4; ++ntp) {
                    unsigned ad = smem_u32(
                        &vs[(kc*16 + lr8 + lm1*8)*SKS2 + ntp*16 + lm2*8]);
                    ldsm_x4_t(vb[ntp*2][0], vb[ntp*2][1],
                              vb[ntp*2+1][0], vb[ntp*2+1][1], ad);
                }
                #pragma unroll
                for (int nt = 0; nt < 8; ++nt)
                    mma_f16(o[nt], pa0, pa1, pa2, pa3, vb[nt][0], vb[nt][1]);
            }
        }
    }

    // Store partials (fp16) + per-row m, l
    const size_t pbase = ((size_t)(b*NQ2 + i)*MAXC2 + c) * (QT*Dc);
    #pragma unroll
    for (int nt = 0; nt < 8; ++nt) {
        const int colb = nt*8 + 2*tg;
        *(unsigned*)&g_Op2h[pbase + (size_t)(w*16 + g    )*Dc + colb] =
            packh2(o[nt][0], o[nt][1]);
        *(unsigned*)&g_Op2h[pbase + (size_t)(w*16 + g + 8)*Dc + colb] =
            packh2(o[nt][2], o[nt][3]);
    }
    if (tg == 0) {
        const size_t rb = ((size_t)(b*NQ2 + i)*MAXC2 + c) * QT + w*16;
        g_m2[rb + g]     = m0v;  g_l2[rb + g]     = l0;
        g_m2[rb + g + 8] = m1v;  g_l2[rb + g + 8] = l1;
    }
}

// ---------------------------------------------------------------------------
// Kernel 3: combine fp16 split-KV partials. grid = (NQ2, B, 8), block 256.
// One uint2 (4 fp16 cols) per thread -> 512 CTAs (R6/R11-proven parallelism).
// ---------------------------------------------------------------------------
__global__ __launch_bounds__(256) void combine_kernel(float* __restrict__ out)
{
    const int i = blockIdx.x;
    const int b = blockIdx.y;
    const int nc = (2*(i+1) + SCH - 1) / SCH;
    const size_t cb = (size_t)(b*NQ2 + i) * MAXC2;

    const int f = blockIdx.z * 256 + threadIdx.x;   // [0, 2048)
    const int row = f >> 4;
    const int grp = f & 15;                          // 4-col group

    float M = -1e30f;
    float mm[MAXC2];
    #pragma unroll
    for (int cc = 0; cc < MAXC2; ++cc) {
        if (cc < nc) {
            mm[cc] = g_m2[(cb + cc)*QT + row];
            M = fmaxf(M, mm[cc]);
        }
    }
    float L = 0.f;
    float o0 = 0.f, o1 = 0.f, o2 = 0.f, o3 = 0.f;
    #pragma unroll
    for (int cc = 0; cc < MAXC2; ++cc) {
        if (cc < nc) {
            float wgt = __expf(mm[cc] - M);
            L += wgt * g_l2[(cb + cc)*QT + row];
            uint2 p = *(const uint2*)&g_Op2h[(cb + cc)*(QT*Dc) + row*Dc + grp*4];
            float2 v0 = __half22float2(*(__half2*)&p.x);
            float2 v1 = __half22float2(*(__half2*)&p.y);
            o0 += wgt*v0.x; o1 += wgt*v0.y;
            o2 += wgt*v1.x; o3 += wgt*v1.y;
        }
    }
    float inv = 1.f / L;
    float4 o;
    o.x = o0*inv; o.y = o1*inv; o.z = o2*inv; o.w = o3*inv;
    ((float4*)out)[((size_t)b*Tc + i*QT + row)*(Dc/4) + grp] = o;
}

// ---------------------------------------------------------------------------
extern "C" void kernel_launch(void* const* d_in, const int* in_sizes, int n_in,
                              void* d_out, int out_size)
{
    const float* x  = (const float*)d_in[0];
    const float* Wq = (const float*)d_in[1];
    const float* bq = (const float*)d_in[2];
    const float* Wk = (const float*)d_in[3];
    const float* bk = (const float*)d_in[4];
    const float* Wv = (const float*)d_in[5];
    const float* bv = (const float*)d_in[6];
    float* out = (float*)d_out;

    prep_kernel<<<4096 + 768, 256>>>(x, Wq, Wk, Wv);

    const int qkv_smem = 4*64*SA2 * (int)sizeof(__half);   // 20,480 B
    cudaFuncSetAttribute(qkv_kernel, cudaFuncAttributeMaxDynamicSharedMemorySize, qkv_smem);
    dim3 g1(BT/64, 3);
    qkv_kernel<<<g1, 128, qkv_smem>>>(bq, bk, bv);

    const int attn_smem = 4*64*SKS2 * (int)sizeof(__half); // 36,864 B
    cudaFuncSetAttribute(attn_kernel, cudaFuncAttributeMaxDynamicSharedMemorySize, attn_smem);
    dim3 g2(MAXC2, NQ2, Bc);
    attn_kernel<<<g2, 256, attn_smem>>>();

    dim3 g3(NQ2, Bc, 8);
    combine_kernel<<<g3, 256>>>(out);
}